// round 6
// baseline (speedup 1.0000x reference)
#include <cuda_runtime.h>
#include <cuda_fp16.h>

#define NUM_PL 50000
#define NUM_TR 100000
#define NUM_AR 10000
#define NTOT   160000
#define HID    64
#define FEAT   128
#define OFF_TR NUM_PL
#define OFF_AR (NUM_PL + NUM_TR)
#define NEDGE  4200000

// Scratch (device globals — no allocation allowed)
__device__ __align__(16) float  g_X [(size_t)NTOT * HID];   // fp32 layer-0 input
__device__ __align__(16) float  g_X2[(size_t)NTOT * HID];   // fp32 layer-0 output
__device__ __align__(16) __half g_Xh [(size_t)NTOT * HID];  // half mirror of g_X
__device__ __align__(16) __half g_X2h[(size_t)NTOT * HID];  // half mirror of g_X2
__device__ int g_DEG[NTOT];
__device__ int g_CUR[NTOT];
__device__ int g_ROWPTR[NTOT + 1];
__device__ int g_ADJ[NEDGE];

// ---------------------------------------------------------------------------
__global__ void zero_kernel() {
    int i = blockIdx.x * blockDim.x + threadIdx.x;
    int stride = gridDim.x * blockDim.x;
    for (int k = i; k < NTOT; k += stride) { g_DEG[k] = 0; g_CUR[k] = 0; }
}

// x[node] = emb[node] + type_row ; also write half mirror
__global__ void init_emb_kernel(const float* __restrict__ emb,
                                const float* __restrict__ te_row,
                                int nodeOff, int n) {
    int i = blockIdx.x * blockDim.x + threadIdx.x;
    if (i < n) {
        float v = emb[i] + te_row[i & (HID - 1)];
        g_X [(size_t)nodeOff * HID + i] = v;
        g_Xh[(size_t)nodeOff * HID + i] = __float2half_rn(v);
    }
}

// tracks: x = track_x @ W^T + b + type_emb[1]; 32 tracks/block, 2 outs/thread.
#define TLP (FEAT + 4)
__global__ void track_linear_kernel(const float* __restrict__ tx,
                                    const float* __restrict__ W,
                                    const float* __restrict__ b,
                                    const float* __restrict__ te) {
    __shared__ float shW[HID * TLP];
    __shared__ float shR[32 * FEAT];
    int tid = threadIdx.x;
    for (int i = tid; i < HID * FEAT; i += 256) {
        int j = i >> 7, k = i & (FEAT - 1);
        shW[j * TLP + k] = W[i];
    }
    int base = blockIdx.x * 32;
    const float4* tx4 = reinterpret_cast<const float4*>(tx) + (size_t)base * (FEAT / 4);
    float4* shR4 = reinterpret_cast<float4*>(shR);
    for (int i = tid; i < 32 * FEAT / 4; i += 256) shR4[i] = tx4[i];
    int j0 = tid & 31, g = tid >> 5;
    float bias0 = b[j0] + te[HID + j0];
    float bias1 = b[j0 + 32] + te[HID + j0 + 32];
    __syncthreads();
    float acc0[4] = {bias0, bias0, bias0, bias0};
    float acc1[4] = {bias1, bias1, bias1, bias1};
#pragma unroll
    for (int k4 = 0; k4 < FEAT; k4 += 4) {
        float4 w0 = *reinterpret_cast<const float4*>(&shW[j0 * TLP + k4]);
        float4 w1 = *reinterpret_cast<const float4*>(&shW[(j0 + 32) * TLP + k4]);
#pragma unroll
        for (int t = 0; t < 4; t++) {
            float4 r = *reinterpret_cast<const float4*>(&shR[(g * 4 + t) * FEAT + k4]);
            acc0[t] += r.x * w0.x + r.y * w0.y + r.z * w0.z + r.w * w0.w;
            acc1[t] += r.x * w1.x + r.y * w1.y + r.z * w1.z + r.w * w1.w;
        }
    }
#pragma unroll
    for (int t = 0; t < 4; t++) {
        size_t row = (size_t)(OFF_TR + base + g * 4 + t) * HID;
        g_X [row + j0]      = acc0[t];
        g_X [row + j0 + 32] = acc1[t];
        g_Xh[row + j0]      = __float2half_rn(acc0[t]);
        g_Xh[row + j0 + 32] = __float2half_rn(acc1[t]);
    }
}

__global__ void deg_kernel(const int* __restrict__ A, const int* __restrict__ B,
                           int n, int offA, int offB) {
    int i = blockIdx.x * blockDim.x + threadIdx.x;
    if (i < n) {
        atomicAdd(&g_DEG[A[i] + offA], 1);
        atomicAdd(&g_DEG[B[i] + offB], 1);
    }
}

// Single-block exclusive scan DEG -> ROWPTR (int4 vectorized sums)
__global__ void scan_kernel() {
    __shared__ int s[1024];
    int tid = threadIdx.x;
    const int CH = 160;                 // 1024*160 = 163840 >= NTOT
    int beg = tid * CH;
    int end = beg + CH; if (end > NTOT) end = NTOT; if (beg > NTOT) beg = NTOT;
    int sum = 0;
    const int4* d4 = reinterpret_cast<const int4*>(g_DEG);
    if (end == beg + CH) {              // full, aligned chunk
#pragma unroll 8
        for (int i = 0; i < CH / 4; i++) {
            int4 v = d4[beg / 4 + i];
            sum += v.x + v.y + v.z + v.w;
        }
    } else {
        for (int i = beg; i < end; i++) sum += g_DEG[i];
    }
    s[tid] = sum;
    __syncthreads();
    for (int off = 1; off < 1024; off <<= 1) {
        int v = (tid >= off) ? s[tid - off] : 0;
        __syncthreads();
        s[tid] += v;
        __syncthreads();
    }
    int run = (tid == 0) ? 0 : s[tid - 1];
    for (int i = beg; i < end; i++) { g_ROWPTR[i] = run; run += g_DEG[i]; }
    if (tid == 1023) g_ROWPTR[NTOT] = run;
}

__global__ void fill_kernel(const int* __restrict__ A, const int* __restrict__ B,
                            int n, int offA, int offB) {
    int i = blockIdx.x * blockDim.x + threadIdx.x;
    if (i < n) {
        int a = A[i] + offA, b = B[i] + offB;
        int pa = atomicAdd(&g_CUR[a], 1);
        g_ADJ[g_ROWPTR[a] + pa] = b;
        int pb = atomicAdd(&g_CUR[b], 1);
        g_ADJ[g_ROWPTR[b] + pb] = a;
    }
}

// Fused SAGE layer, fp16 gather path. 16 nodes/block, 256 threads.
//   gather: warp handles 2 nodes; per node, 8 lanes/row-quarter x 4 edge
//           substreams, unroll x2 -> 8 LDG.128 in flight per warp.
//   GEMM:   out = relu(mean(agg)@Wl^T + bl + x@Wr^T)  (all fp32)
#define UWP (HID + 4)
__global__ void fused_layer_kernel(const float* __restrict__ Xin,
                                   const __half* __restrict__ Xinh,
                                   float* __restrict__ Xout,
                                   __half* __restrict__ Xouth,
                                   const float* __restrict__ Wl,
                                   const float* __restrict__ bl,
                                   const float* __restrict__ Wr) {
    __shared__ float shWl[HID * UWP];
    __shared__ float shWr[HID * UWP];
    __shared__ float shA[16 * HID];
    __shared__ float shX[16 * HID];
    int tid = threadIdx.x;
    int base = blockIdx.x * 16;
    for (int i = tid; i < HID * HID; i += 256) {
        int j = i >> 6, k = i & 63;
        shWl[j * UWP + k] = Wl[i];
        shWr[j * UWP + k] = Wr[i];
    }
    {   // self rows (fp32), coalesced
        const float4* Xin4 = reinterpret_cast<const float4*>(Xin);
        reinterpret_cast<float4*>(shX)[tid] = Xin4[(size_t)base * 16 + tid];
    }
    // gather (fp16 rows, fp32 accumulate)
    {
        int warp = tid >> 5, lane = tid & 31;
        int q = lane & 7;           // 16B chunk (8 halfs) within 128B row
        int sub = lane >> 3;        // 0..3 edge substreams
        const uint4* Xh4 = reinterpret_cast<const uint4*>(Xinh);  // 8 uint4/row
#pragma unroll
        for (int i2 = 0; i2 < 2; i2++) {
            int nl = warp * 2 + i2;
            int node = base + nl;
            int beg = g_ROWPTR[node], end = g_ROWPTR[node + 1];
            float acc[8];
#pragma unroll
            for (int z = 0; z < 8; z++) acc[z] = 0.f;
            int e = beg + sub;
            for (; e + 4 < end; e += 8) {
                int s0 = g_ADJ[e], s1 = g_ADJ[e + 4];
                uint4 v0 = Xh4[(size_t)s0 * 8 + q];
                uint4 v1 = Xh4[(size_t)s1 * 8 + q];
                const __half2* h0 = reinterpret_cast<const __half2*>(&v0);
                const __half2* h1 = reinterpret_cast<const __half2*>(&v1);
#pragma unroll
                for (int z = 0; z < 4; z++) {
                    float2 f0 = __half22float2(h0[z]);
                    float2 f1 = __half22float2(h1[z]);
                    acc[2 * z]     += f0.x + f1.x;
                    acc[2 * z + 1] += f0.y + f1.y;
                }
            }
            if (e < end) {
                uint4 v = Xh4[(size_t)g_ADJ[e] * 8 + q];
                const __half2* h = reinterpret_cast<const __half2*>(&v);
#pragma unroll
                for (int z = 0; z < 4; z++) {
                    float2 f = __half22float2(h[z]);
                    acc[2 * z]     += f.x;
                    acc[2 * z + 1] += f.y;
                }
            }
#pragma unroll
            for (int z = 0; z < 8; z++) {
                acc[z] += __shfl_xor_sync(0xffffffffu, acc[z], 8);
                acc[z] += __shfl_xor_sync(0xffffffffu, acc[z], 16);
            }
            if (lane < 8) {
                int d = end - beg;
                float inv = (d > 0) ? 1.0f / (float)d : 0.0f;
                float4 r0 = make_float4(acc[0] * inv, acc[1] * inv, acc[2] * inv, acc[3] * inv);
                float4 r1 = make_float4(acc[4] * inv, acc[5] * inv, acc[6] * inv, acc[7] * inv);
                float4* dst = reinterpret_cast<float4*>(&shA[nl * HID + q * 8]);
                dst[0] = r0;
                dst[1] = r1;
            }
        }
    }
    __syncthreads();
    // GEMM
    int j = tid & 63, g = tid >> 6;
    float bias = bl[j];
    float acc[4] = {bias, bias, bias, bias};
#pragma unroll
    for (int k4 = 0; k4 < HID; k4 += 4) {
        float4 wl = *reinterpret_cast<const float4*>(&shWl[j * UWP + k4]);
        float4 wr = *reinterpret_cast<const float4*>(&shWr[j * UWP + k4]);
#pragma unroll
        for (int t = 0; t < 4; t++) {
            int nn = g * 4 + t;
            float4 a = *reinterpret_cast<const float4*>(&shA[nn * HID + k4]);
            float4 x = *reinterpret_cast<const float4*>(&shX[nn * HID + k4]);
            acc[t] += a.x * wl.x + a.y * wl.y + a.z * wl.z + a.w * wl.w
                    + x.x * wr.x + x.y * wr.y + x.z * wr.z + x.w * wr.w;
        }
    }
#pragma unroll
    for (int t = 0; t < 4; t++) {
        size_t row = (size_t)(base + g * 4 + t) * HID;
        float v = fmaxf(acc[t], 0.f);
        Xout[row + j] = v;
        if (Xouth) Xouth[row + j] = __float2half_rn(v);
    }
}

// ---------------------------------------------------------------------------
extern "C" void kernel_launch(void* const* d_in, const int* in_sizes, int n_in,
                              void* d_out, int out_size) {
    const float* track_x      = (const float*)d_in[0];
    const int*   pl_tr_src    = (const int*)d_in[1];
    const int*   pl_tr_dst    = (const int*)d_in[2];
    const int*   tr_ar_src    = (const int*)d_in[3];
    const int*   tr_ar_dst    = (const int*)d_in[4];
    const float* playlist_emb = (const float*)d_in[5];
    const float* artist_emb   = (const float*)d_in[6];
    const float* track_W      = (const float*)d_in[7];
    const float* track_b      = (const float*)d_in[8];
    const float* type_emb     = (const float*)d_in[9];
    const float* conv_Wl      = (const float*)d_in[10];
    const float* conv_bl      = (const float*)d_in[11];
    const float* conv_Wr      = (const float*)d_in[12];
    float* out = (float*)d_out;

    int nE1 = in_sizes[1];
    int nE2 = in_sizes[3];

    // init + CSR build
    zero_kernel<<<320, 256>>>();
    init_emb_kernel<<<(NUM_PL * HID + 255) / 256, 256>>>(playlist_emb, type_emb, 0, NUM_PL * HID);
    init_emb_kernel<<<(NUM_AR * HID + 255) / 256, 256>>>(artist_emb, type_emb + 2 * HID, OFF_AR, NUM_AR * HID);
    track_linear_kernel<<<NUM_TR / 32, 256>>>(track_x, track_W, track_b, type_emb);
    deg_kernel<<<(nE1 + 255) / 256, 256>>>(pl_tr_src, pl_tr_dst, nE1, 0, OFF_TR);
    deg_kernel<<<(nE2 + 255) / 256, 256>>>(tr_ar_src, tr_ar_dst, nE2, OFF_TR, OFF_AR);
    scan_kernel<<<1, 1024>>>();
    fill_kernel<<<(nE1 + 255) / 256, 256>>>(pl_tr_src, pl_tr_dst, nE1, 0, OFF_TR);
    fill_kernel<<<(nE2 + 255) / 256, 256>>>(tr_ar_src, tr_ar_dst, nE2, OFF_TR, OFF_AR);

    // two fused SAGE layers
    float*  X1;   cudaGetSymbolAddress((void**)&X1,  g_X);
    float*  X2;   cudaGetSymbolAddress((void**)&X2,  g_X2);
    __half* X1h;  cudaGetSymbolAddress((void**)&X1h, g_Xh);
    __half* X2h;  cudaGetSymbolAddress((void**)&X2h, g_X2h);
    fused_layer_kernel<<<NTOT / 16, 256>>>(X1, X1h, X2, X2h, conv_Wl, conv_bl, conv_Wr);
    fused_layer_kernel<<<NTOT / 16, 256>>>(X2, X2h, out, ((__half*)0),
                                           conv_Wl + HID * HID, conv_bl + HID,
                                           conv_Wr + HID * HID);
}